// round 2
// baseline (speedup 1.0000x reference)
#include <cuda_runtime.h>

// OctonionLinear as GEMM: C[512,4096] = A[512,4096] * B[4096,4096]
// A = x (row-major). B(kk, n) lives at w[(n>>3)*32768 + kk*8 + (n&7)]
// (weight [512,512,8,8] == 512 contiguous [4096,8] row-major column panels).
// bias flattened to [4096] adds per output column.

#define BM 128
#define BN 128
#define BK 16
#define KDIM 4096
#define APITCH 132   // As row pitch (multiple of 4 for float4 reads, offset banks on store)

__global__ __launch_bounds__(256, 2)
void octonion_gemm_kernel(const float* __restrict__ x,
                          const float* __restrict__ w,
                          const float* __restrict__ bias,
                          float* __restrict__ out)
{
    __shared__ float As[BK * APITCH];   // [kk][m], transposed A tile
    __shared__ float Bs[BK * BN];       // [kk][n]

    const int tid  = threadIdx.x;
    const int tx   = tid & 15;          // 16 column groups
    const int ty   = tid >> 4;          // 16 row groups
    const int row0 = blockIdx.y * BM;
    const int col0 = blockIdx.x * BN;

    float acc[8][8];
    #pragma unroll
    for (int i = 0; i < 8; ++i)
        #pragma unroll
        for (int j = 0; j < 8; ++j)
            acc[i][j] = 0.0f;

    for (int k0 = 0; k0 < KDIM; k0 += BK) {
        // ---- load A tile (transposed into As[kk][m]) ----
        #pragma unroll
        for (int it = 0; it < 2; ++it) {
            const int chunk = tid + it * 256;       // 512 float4 chunks
            const int m  = chunk >> 2;              // 0..127
            const int kk = (chunk & 3) << 2;        // 0,4,8,12
            const float4 v = *reinterpret_cast<const float4*>(
                x + (size_t)(row0 + m) * KDIM + k0 + kk);
            As[(kk + 0) * APITCH + m] = v.x;
            As[(kk + 1) * APITCH + m] = v.y;
            As[(kk + 2) * APITCH + m] = v.z;
            As[(kk + 3) * APITCH + m] = v.w;
        }
        // ---- load B tile ----
        #pragma unroll
        for (int it = 0; it < 2; ++it) {
            const int chunk = tid + it * 256;       // 512 float4 chunks
            const int kk = chunk >> 5;              // 0..15
            const int c4 = (chunk & 31) << 2;       // 0..124 step 4
            const int n  = col0 + c4;
            const int oi = n >> 3;                  // output octonion index
            const int kc = n & 7;                   // 0 or 4
            const float4 v = *reinterpret_cast<const float4*>(
                w + (size_t)oi * 32768 + (size_t)(k0 + kk) * 8 + kc);
            *reinterpret_cast<float4*>(&Bs[kk * BN + c4]) = v;
        }
        __syncthreads();

        // ---- compute 8x8 micro-tile per thread ----
        #pragma unroll
        for (int kk = 0; kk < BK; ++kk) {
            float a[8], b[8];
            const float4 a0 = *reinterpret_cast<const float4*>(&As[kk * APITCH + ty * 4]);
            const float4 a1 = *reinterpret_cast<const float4*>(&As[kk * APITCH + 64 + ty * 4]);
            const float4 b0 = *reinterpret_cast<const float4*>(&Bs[kk * BN + tx * 4]);
            const float4 b1 = *reinterpret_cast<const float4*>(&Bs[kk * BN + 64 + tx * 4]);
            a[0] = a0.x; a[1] = a0.y; a[2] = a0.z; a[3] = a0.w;
            a[4] = a1.x; a[5] = a1.y; a[6] = a1.z; a[7] = a1.w;
            b[0] = b0.x; b[1] = b0.y; b[2] = b0.z; b[3] = b0.w;
            b[4] = b1.x; b[5] = b1.y; b[6] = b1.z; b[7] = b1.w;
            #pragma unroll
            for (int i = 0; i < 8; ++i)
                #pragma unroll
                for (int j = 0; j < 8; ++j)
                    acc[i][j] = fmaf(a[i], b[j], acc[i][j]);
        }
        __syncthreads();
    }

    // ---- epilogue: + bias, float4 stores ----
    #pragma unroll
    for (int ri = 0; ri < 8; ++ri) {
        const int r = row0 + ((ri < 4) ? (ty * 4 + ri) : (64 + ty * 4 + ri - 4));
        #pragma unroll
        for (int ch = 0; ch < 2; ++ch) {
            const int c = col0 + ch * 64 + tx * 4;
            const float4 bb = *reinterpret_cast<const float4*>(bias + c);
            float4 o;
            o.x = acc[ri][ch * 4 + 0] + bb.x;
            o.y = acc[ri][ch * 4 + 1] + bb.y;
            o.z = acc[ri][ch * 4 + 2] + bb.z;
            o.w = acc[ri][ch * 4 + 3] + bb.w;
            *reinterpret_cast<float4*>(out + (size_t)r * KDIM + c) = o;
        }
    }
}

extern "C" void kernel_launch(void* const* d_in, const int* in_sizes, int n_in,
                              void* d_out, int out_size)
{
    const float* x    = (const float*)d_in[0];   // [512, 4096]
    const float* w    = (const float*)d_in[1];   // [512, 512, 8, 8]
    const float* bias = (const float*)d_in[2];   // [512, 8] -> flat [4096]
    float* out = (float*)d_out;                  // [512, 4096]

    dim3 grid(4096 / BN, 512 / BM);              // (32, 4)
    octonion_gemm_kernel<<<grid, 256>>>(x, w, bias, out);
}

// round 4
// speedup vs baseline: 2.7326x; 2.7326x over previous
#include <cuda_runtime.h>
#include <cstdint>

#define KDIM 4096
#define NKB  128          // 4096 / BK, BK = 32
#define SMEM_BYTES 65536  // 2 stages x (A 16KB + B 16KB)

__device__ __forceinline__ float f2tf32(float f) {
    uint32_t u;
    asm("cvt.rna.tf32.f32 %0, %1;" : "=r"(u) : "f"(f));
    return __uint_as_float(u);
}

__device__ __forceinline__ void mma_tf32(float* d, const uint32_t* a, const uint32_t* b) {
    asm volatile(
        "mma.sync.aligned.m16n8k8.row.col.f32.tf32.tf32.f32 "
        "{%0,%1,%2,%3}, {%4,%5,%6,%7}, {%8,%9}, {%0,%1,%2,%3};"
        : "+f"(d[0]), "+f"(d[1]), "+f"(d[2]), "+f"(d[3])
        : "r"(a[0]), "r"(a[1]), "r"(a[2]), "r"(a[3]),
          "r"(b[0]), "r"(b[1]));
}

// Smem per stage (floats): A frag-ordered [8 mtiles][4 ktiles][32 t][4 regs] = 4096
//                          B frag-ordered [16 ntiles][4 ktiles][32 t][2 regs] = 4096
__global__ __launch_bounds__(256, 1)
void octonion_mma_kernel(const float* __restrict__ x,
                         const float* __restrict__ w,
                         const float* __restrict__ bias,
                         float* __restrict__ out)
{
    extern __shared__ float sm[];

    const int tid  = threadIdx.x;
    const int lane = tid & 31;
    const int warp = tid >> 5;
    const int wm   = warp >> 2;          // 0..1 : 64 rows each
    const int wn   = warp & 3;           // 0..3 : 32 cols each
    const int row0 = blockIdx.y * 128;
    const int col0 = blockIdx.x * 128;

    const float* xb = x + (size_t)row0 * KDIM;
    const float* wb = w + (size_t)(col0 >> 3) * 32768;

    // ---- per-thread loader descriptors (4 float4 chunks each for A and B) ----
    int gA[4], sA[4], gB[4], sB[4];
    #pragma unroll
    for (int i = 0; i < 4; ++i) {
        const int c = tid + i * 256;
        // A chunk: row m (0..127), float4 index kk4 (0..7) within BK=32
        const int m = c >> 3, kk4 = c & 7;
        gA[i] = m * KDIM + kk4 * 4;
        const int atile = (m >> 4) * 4 + (kk4 >> 1);
        const int areg  = (kk4 & 1) * 2 + ((m >> 3) & 1);
        sA[i] = atile * 128 + (m & 7) * 16 + areg;   // + j*4 per element j
        // B chunk: local octonion oi (0..15), k-row kk (0..31), half h (0..1)
        const int oi = c >> 6, kk = (c >> 1) & 31, h = c & 1;
        gB[i] = oi * 32768 + kk * 8 + h * 4;
        const int btile = oi * 4 + (kk >> 3);
        const int breg  = (kk >> 2) & 1;
        sB[i] = btile * 64 + (h * 32 + (kk & 3) * 2) + breg;  // + j*8 per element j
    }

    float acc[4][4][4];
    #pragma unroll
    for (int i = 0; i < 4; ++i)
        #pragma unroll
        for (int j = 0; j < 4; ++j)
            #pragma unroll
            for (int r = 0; r < 4; ++r)
                acc[i][j][r] = 0.0f;

    float4 ra[4], rb[4];

    // ---- prologue: fill stage 0 ----
    #pragma unroll
    for (int i = 0; i < 4; ++i) {
        ra[i] = *reinterpret_cast<const float4*>(xb + gA[i]);
        rb[i] = *reinterpret_cast<const float4*>(wb + gB[i]);
    }
    #pragma unroll
    for (int i = 0; i < 4; ++i) {
        float* SA = sm + sA[i];
        SA[0]  = f2tf32(ra[i].x);
        SA[4]  = f2tf32(ra[i].y);
        SA[8]  = f2tf32(ra[i].z);
        SA[12] = f2tf32(ra[i].w);
        float* SB = sm + 4096 + sB[i];
        SB[0]  = f2tf32(rb[i].x);
        SB[8]  = f2tf32(rb[i].y);
        SB[16] = f2tf32(rb[i].z);
        SB[24] = f2tf32(rb[i].w);
    }
    __syncthreads();

    // ---- main loop: 1 barrier per k-block ----
    for (int kb = 0; kb < NKB; ++kb) {
        const int stage = kb & 1;

        if (kb + 1 < NKB) {
            const float* xk = xb + (kb + 1) * 32;
            const float* wk = wb + (kb + 1) * 256;
            #pragma unroll
            for (int i = 0; i < 4; ++i) {
                ra[i] = *reinterpret_cast<const float4*>(xk + gA[i]);
                rb[i] = *reinterpret_cast<const float4*>(wk + gB[i]);
            }
        }

        // compute on current stage
        const float* S  = sm + stage * 8192;
        const float* SBc = S + 4096;
        #pragma unroll
        for (int ks = 0; ks < 4; ++ks) {
            uint4 av[4];
            uint2 bv[4];
            #pragma unroll
            for (int i = 0; i < 4; ++i)
                av[i] = *reinterpret_cast<const uint4*>(
                    S + ((wm * 4 + i) * 4 + ks) * 128 + lane * 4);
            #pragma unroll
            for (int j = 0; j < 4; ++j)
                bv[j] = *reinterpret_cast<const uint2*>(
                    SBc + ((wn * 4 + j) * 4 + ks) * 64 + lane * 2);
            #pragma unroll
            for (int i = 0; i < 4; ++i)
                #pragma unroll
                for (int j = 0; j < 4; ++j)
                    mma_tf32(acc[i][j],
                             reinterpret_cast<const uint32_t*>(&av[i]),
                             reinterpret_cast<const uint32_t*>(&bv[j]));
        }

        // store prefetched data into the other stage
        if (kb + 1 < NKB) {
            float* T = sm + (stage ^ 1) * 8192;
            #pragma unroll
            for (int i = 0; i < 4; ++i) {
                float* SA = T + sA[i];
                SA[0]  = f2tf32(ra[i].x);
                SA[4]  = f2tf32(ra[i].y);
                SA[8]  = f2tf32(ra[i].z);
                SA[12] = f2tf32(ra[i].w);
                float* SB = T + 4096 + sB[i];
                SB[0]  = f2tf32(rb[i].x);
                SB[8]  = f2tf32(rb[i].y);
                SB[16] = f2tf32(rb[i].z);
                SB[24] = f2tf32(rb[i].w);
            }
        }
        __syncthreads();
    }

    // ---- epilogue: accum regs -> gmem with bias (float2 per store) ----
    #pragma unroll
    for (int i = 0; i < 4; ++i) {
        const int row = row0 + wm * 64 + i * 16 + (lane >> 2);
        #pragma unroll
        for (int j = 0; j < 4; ++j) {
            const int col = col0 + wn * 32 + j * 8 + (lane & 3) * 2;
            const float2 bb = *reinterpret_cast<const float2*>(bias + col);
            float2 o0, o1;
            o0.x = acc[i][j][0] + bb.x;
            o0.y = acc[i][j][1] + bb.y;
            o1.x = acc[i][j][2] + bb.x;
            o1.y = acc[i][j][3] + bb.y;
            *reinterpret_cast<float2*>(out + (size_t)row * KDIM + col) = o0;
            *reinterpret_cast<float2*>(out + (size_t)(row + 8) * KDIM + col) = o1;
        }
    }
}

extern "C" void kernel_launch(void* const* d_in, const int* in_sizes, int n_in,
                              void* d_out, int out_size)
{
    const float* x    = (const float*)d_in[0];   // [512, 4096]
    const float* w    = (const float*)d_in[1];   // [512, 512, 8, 8]
    const float* bias = (const float*)d_in[2];   // [512, 8] -> flat [4096]
    float* out = (float*)d_out;                  // [512, 4096]

    cudaFuncSetAttribute(octonion_mma_kernel,
                         cudaFuncAttributeMaxDynamicSharedMemorySize, SMEM_BYTES);
    dim3 grid(KDIM / 128, 512 / 128);            // (32, 4) = 128 CTAs
    octonion_mma_kernel<<<grid, 256, SMEM_BYTES>>>(x, w, bias, out);
}

// round 5
// speedup vs baseline: 3.5460x; 1.2977x over previous
#include <cuda_runtime.h>
#include <cstdint>

#define KDIM 4096
#define BK 32
#define NKB 128
#define PA 36                         // A tile row pitch (floats): banks = lane, conflict-free
#define PB 136                        // B tile row pitch (floats): banks = (k&3)*8+(n&7)
#define A_FLOATS (128 * PA)           // 4608
#define B_FLOATS (32 * PB)            // 4352
#define STG_FLOATS (A_FLOATS + B_FLOATS)  // 8960
#define NSTAGE 4
#define SMEM_BYTES (NSTAGE * STG_FLOATS * 4)  // 143360

__device__ __forceinline__ uint32_t smem_u32(const void* p) {
    uint32_t a;
    asm("{ .reg .u64 t; cvta.to.shared.u64 t, %1; cvt.u32.u64 %0, t; }" : "=r"(a) : "l"(p));
    return a;
}
__device__ __forceinline__ void cp16(uint32_t dst, const void* src) {
    asm volatile("cp.async.cg.shared.global [%0], [%1], 16;" :: "r"(dst), "l"(src));
}
__device__ __forceinline__ uint32_t ld_tf32(uint32_t addr) {
    float f; uint32_t u;
    asm volatile("ld.shared.b32 %0, [%1];" : "=f"(f) : "r"(addr));
    asm("cvt.rna.tf32.f32 %0, %1;" : "=r"(u) : "f"(f));
    return u;
}
__device__ __forceinline__ void mma_tf32(float* d, const uint32_t* a, const uint32_t* b) {
    asm volatile(
        "mma.sync.aligned.m16n8k8.row.col.f32.tf32.tf32.f32 "
        "{%0,%1,%2,%3}, {%4,%5,%6,%7}, {%8,%9}, {%0,%1,%2,%3};"
        : "+f"(d[0]), "+f"(d[1]), "+f"(d[2]), "+f"(d[3])
        : "r"(a[0]), "r"(a[1]), "r"(a[2]), "r"(a[3]),
          "r"(b[0]), "r"(b[1]));
}

__global__ __launch_bounds__(128, 1)
void octonion_mma_v2(const float* __restrict__ x,
                     const float* __restrict__ w,
                     const float* __restrict__ bias,
                     float* __restrict__ out)
{
    extern __shared__ float sm[];
    const uint32_t sbase = smem_u32(sm);

    const int tid  = threadIdx.x;
    const int lane = tid & 31;
    const int warp = tid >> 5;
    const int wm   = warp >> 1;          // 0..1 -> 64 rows
    const int wn   = warp & 1;           // 0..1 -> 64 cols
    const int row0 = blockIdx.y * 128;
    const int col0 = blockIdx.x * 128;
    const int oct0 = col0 >> 3;

    // ---- loader descriptors (per thread: 8 A chunks, 8 B chunks per k-block) ----
    // A chunk i: row m0+16i, k-quad kk4 (fixed). gmem contiguous 16B, smem natural.
    const int m0  = tid >> 3, kk4 = tid & 7;
    const float* aSrc = x + (size_t)(row0 + m0) * KDIM + kk4 * 4;
    const uint32_t aDst0 = (uint32_t)(m0 * PA + kk4 * 4) * 4;
    // B chunk i: octonion oi0+2i, k-row kkl, n-half h (fixed).
    const int oi0 = tid >> 6, kkl = (tid >> 1) & 31, h = tid & 1;
    const float* bSrc = w + (size_t)(oct0 + oi0) * 32768 + kkl * 8 + h * 4;
    const uint32_t bDst0 = (uint32_t)(A_FLOATS + kkl * PB + oi0 * 8 + h * 4) * 4;

    // ---- fragment base offsets (bytes within a stage) ----
    const uint32_t aFB = (uint32_t)((wm * 64 + (lane >> 2)) * PA + (lane & 3)) * 4;
    const uint32_t bFB = (uint32_t)(A_FLOATS + (lane & 3) * PB + wn * 64 + (lane >> 2)) * 4;

    float acc[4][8][4];
    #pragma unroll
    for (int i = 0; i < 4; ++i)
        #pragma unroll
        for (int j = 0; j < 8; ++j)
            #pragma unroll
            for (int r = 0; r < 4; ++r)
                acc[i][j][r] = 0.0f;

    // ---- prologue: 3 stages in flight ----
    #pragma unroll
    for (int s = 0; s < 3; ++s) {
        const uint32_t so = sbase + s * (STG_FLOATS * 4);
        const float* as = aSrc + s * BK;
        const float* bs = bSrc + s * 256;
        #pragma unroll
        for (int i = 0; i < 8; ++i) {
            cp16(so + aDst0 + i * (16 * PA * 4), as + (size_t)i * 16 * KDIM);
            cp16(so + bDst0 + i * 64,            bs + (size_t)i * 65536);
        }
        asm volatile("cp.async.commit_group;" ::: "memory");
    }

    for (int kb = 0; kb < NKB; ++kb) {
        asm volatile("cp.async.wait_group 2;" ::: "memory");
        __syncthreads();

        const uint32_t so = sbase + (kb & 3) * (STG_FLOATS * 4);
        const uint32_t aS = so + aFB;
        const uint32_t bS = so + bFB;

        #pragma unroll
        for (int ks = 0; ks < 4; ++ks) {
            uint32_t a[4][4], b[8][2];
            #pragma unroll
            for (int mt = 0; mt < 4; ++mt)
                #pragma unroll
                for (int r = 0; r < 4; ++r)
                    a[mt][r] = ld_tf32(aS + (uint32_t)(mt * (16 * PA) + (r & 1) * (8 * PA)
                                                       + ks * 8 + (r >> 1) * 4) * 4);
            #pragma unroll
            for (int nt = 0; nt < 8; ++nt)
                #pragma unroll
                for (int r = 0; r < 2; ++r)
                    b[nt][r] = ld_tf32(bS + (uint32_t)((r * 4 + ks * 8) * PB + nt * 8) * 4);
            #pragma unroll
            for (int mt = 0; mt < 4; ++mt)
                #pragma unroll
                for (int nt = 0; nt < 8; ++nt)
                    mma_tf32(acc[mt][nt], a[mt], b[nt]);
        }

        if (kb + 3 < NKB) {
            const int kn = kb + 3;
            const uint32_t sn = sbase + (kn & 3) * (STG_FLOATS * 4);
            const float* as = aSrc + kn * BK;
            const float* bs = bSrc + kn * 256;
            #pragma unroll
            for (int i = 0; i < 8; ++i) {
                cp16(sn + aDst0 + i * (16 * PA * 4), as + (size_t)i * 16 * KDIM);
                cp16(sn + bDst0 + i * 64,            bs + (size_t)i * 65536);
            }
            asm volatile("cp.async.commit_group;" ::: "memory");
        }
    }

    // ---- epilogue: + bias, float2 stores ----
    #pragma unroll
    for (int mt = 0; mt < 4; ++mt) {
        const int row = row0 + wm * 64 + mt * 16 + (lane >> 2);
        #pragma unroll
        for (int nt = 0; nt < 8; ++nt) {
            const int col = col0 + wn * 64 + nt * 8 + (lane & 3) * 2;
            const float2 bb = *reinterpret_cast<const float2*>(bias + col);
            float2 o0, o1;
            o0.x = acc[mt][nt][0] + bb.x;
            o0.y = acc[mt][nt][1] + bb.y;
            o1.x = acc[mt][nt][2] + bb.x;
            o1.y = acc[mt][nt][3] + bb.y;
            *reinterpret_cast<float2*>(out + (size_t)row * KDIM + col) = o0;
            *reinterpret_cast<float2*>(out + (size_t)(row + 8) * KDIM + col) = o1;
        }
    }
}

extern "C" void kernel_launch(void* const* d_in, const int* in_sizes, int n_in,
                              void* d_out, int out_size)
{
    const float* x    = (const float*)d_in[0];   // [512, 4096]
    const float* w    = (const float*)d_in[1];   // [512, 512, 8, 8]
    const float* bias = (const float*)d_in[2];   // [512, 8] -> flat [4096]
    float* out = (float*)d_out;                  // [512, 4096]

    cudaFuncSetAttribute(octonion_mma_v2,
                         cudaFuncAttributeMaxDynamicSharedMemorySize, SMEM_BYTES);
    dim3 grid(KDIM / 128, 512 / 128);            // (32, 4) = 128 CTAs
    octonion_mma_v2<<<grid, 128, SMEM_BYTES>>>(x, w, bias, out);
}

// round 6
// speedup vs baseline: 3.5694x; 1.0066x over previous
#include <cuda_runtime.h>
#include <cstdint>

#define KDIM 4096
#define BK 32
#define NKB 128
#define PA 36                         // A tile row pitch (floats)
#define PB 136                        // B tile row pitch (floats)
#define A_FLOATS (128 * PA)           // 4608
#define B_FLOATS (32 * PB)            // 4352
#define STG_FLOATS (A_FLOATS + B_FLOATS)  // 8960
#define NSTAGE 4
#define SMEM_BYTES (NSTAGE * STG_FLOATS * 4)  // 143360

__device__ __forceinline__ uint32_t smem_u32(const void* p) {
    uint32_t a;
    asm("{ .reg .u64 t; cvta.to.shared.u64 t, %1; cvt.u32.u64 %0, t; }" : "=r"(a) : "l"(p));
    return a;
}
__device__ __forceinline__ void cp16(uint32_t dst, const void* src) {
    asm volatile("cp.async.cg.shared.global [%0], [%1], 16;" :: "r"(dst), "l"(src));
}
__device__ __forceinline__ uint32_t ld_tf32(uint32_t addr) {
    float f; uint32_t u;
    asm volatile("ld.shared.b32 %0, [%1];" : "=f"(f) : "r"(addr));
    asm("cvt.rna.tf32.f32 %0, %1;" : "=r"(u) : "f"(f));
    return u;
}
__device__ __forceinline__ void mma_tf32(float* d, const uint32_t* a, const uint32_t* b) {
    asm volatile(
        "mma.sync.aligned.m16n8k8.row.col.f32.tf32.tf32.f32 "
        "{%0,%1,%2,%3}, {%4,%5,%6,%7}, {%8,%9}, {%0,%1,%2,%3};"
        : "+f"(d[0]), "+f"(d[1]), "+f"(d[2]), "+f"(d[3])
        : "r"(a[0]), "r"(a[1]), "r"(a[2]), "r"(a[3]),
          "r"(b[0]), "r"(b[1]));
}

__global__ __launch_bounds__(256, 1)
void octonion_mma_v3(const float* __restrict__ x,
                     const float* __restrict__ w,
                     const float* __restrict__ bias,
                     float* __restrict__ out)
{
    extern __shared__ float sm[];
    const uint32_t sbase = smem_u32(sm);

    const int tid  = threadIdx.x;
    const int lane = tid & 31;
    const int warp = tid >> 5;
    const int wm   = warp >> 2;          // 0..1 -> 64-row strip
    const int wn   = warp & 3;           // 0..3 -> 32-col strip
    const int row0 = blockIdx.y * 128;
    const int col0 = blockIdx.x * 128;
    const int oct0 = col0 >> 3;

    // ---- loader descriptors: 4 A chunks + 4 B chunks per thread per k-block ----
    // A: row m0 + 32*i, k-quad kk4 (16B contiguous in gmem and smem)
    const int m0  = tid >> 3, kk4 = tid & 7;
    const float* aSrc = x + (size_t)(row0 + m0) * KDIM + kk4 * 4;
    const uint32_t aDst0 = (uint32_t)(m0 * PA + kk4 * 4) * 4;
    // B: octonion oct0 + oi0 + 4*i, k-row kkl, n-half h
    const int oi0 = tid >> 6, kkl = (tid >> 1) & 31, h = tid & 1;
    const float* bSrc = w + (size_t)(oct0 + oi0) * 32768 + kkl * 8 + h * 4;
    const uint32_t bDst0 = (uint32_t)(A_FLOATS + kkl * PB + oi0 * 8 + h * 4) * 4;

    // ---- fragment base offsets (bytes within a stage) ----
    const uint32_t aFB = (uint32_t)((wm * 64 + (lane >> 2)) * PA + (lane & 3)) * 4;
    const uint32_t bFB = (uint32_t)(A_FLOATS + (lane & 3) * PB + wn * 32 + (lane >> 2)) * 4;

    float acc[4][4][4];
    #pragma unroll
    for (int i = 0; i < 4; ++i)
        #pragma unroll
        for (int j = 0; j < 4; ++j)
            #pragma unroll
            for (int r = 0; r < 4; ++r)
                acc[i][j][r] = 0.0f;

    // ---- prologue: 3 stages in flight ----
    #pragma unroll
    for (int s = 0; s < 3; ++s) {
        const uint32_t so = sbase + s * (STG_FLOATS * 4);
        const float* as = aSrc + s * BK;
        const float* bs = bSrc + s * 256;
        #pragma unroll
        for (int i = 0; i < 4; ++i) {
            cp16(so + aDst0 + i * (32 * PA * 4), as + (size_t)i * 32 * KDIM);
            cp16(so + bDst0 + i * 128,           bs + (size_t)i * 131072);
        }
        asm volatile("cp.async.commit_group;" ::: "memory");
    }

    for (int kb = 0; kb < NKB; ++kb) {
        asm volatile("cp.async.wait_group 2;" ::: "memory");
        __syncthreads();

        const uint32_t aS = sbase + (kb & 3) * (STG_FLOATS * 4) + aFB;
        const uint32_t bS = sbase + (kb & 3) * (STG_FLOATS * 4) + bFB;

        #pragma unroll
        for (int ks = 0; ks < 4; ++ks) {
            uint32_t a[4][4], b[4][2];
            #pragma unroll
            for (int mt = 0; mt < 4; ++mt)
                #pragma unroll
                for (int r = 0; r < 4; ++r)
                    a[mt][r] = ld_tf32(aS + (uint32_t)(mt * (16 * PA) + (r & 1) * (8 * PA)
                                                       + ks * 8 + (r >> 1) * 4) * 4);
            #pragma unroll
            for (int nt = 0; nt < 4; ++nt)
                #pragma unroll
                for (int r = 0; r < 2; ++r)
                    b[nt][r] = ld_tf32(bS + (uint32_t)((r * 4 + ks * 8) * PB + nt * 8) * 4);
            #pragma unroll
            for (int mt = 0; mt < 4; ++mt)
                #pragma unroll
                for (int nt = 0; nt < 4; ++nt)
                    mma_tf32(acc[mt][nt], a[mt], b[nt]);
        }

        if (kb + 3 < NKB) {
            const int kn = kb + 3;
            const uint32_t sn = sbase + (kn & 3) * (STG_FLOATS * 4);
            const float* as = aSrc + kn * BK;
            const float* bs = bSrc + kn * 256;
            #pragma unroll
            for (int i = 0; i < 4; ++i) {
                cp16(sn + aDst0 + i * (32 * PA * 4), as + (size_t)i * 32 * KDIM);
                cp16(sn + bDst0 + i * 128,           bs + (size_t)i * 131072);
            }
            asm volatile("cp.async.commit_group;" ::: "memory");
        }
    }

    // ---- epilogue: + bias, float2 stores ----
    #pragma unroll
    for (int mt = 0; mt < 4; ++mt) {
        const int row = row0 + wm * 64 + mt * 16 + (lane >> 2);
        #pragma unroll
        for (int nt = 0; nt < 4; ++nt) {
            const int col = col0 + wn * 32 + nt * 8 + (lane & 3) * 2;
            const float2 bb = *reinterpret_cast<const float2*>(bias + col);
            float2 o0, o1;
            o0.x = acc[mt][nt][0] + bb.x;
            o0.y = acc[mt][nt][1] + bb.y;
            o1.x = acc[mt][nt][2] + bb.x;
            o1.y = acc[mt][nt][3] + bb.y;
            *reinterpret_cast<float2*>(out + (size_t)row * KDIM + col) = o0;
            *reinterpret_cast<float2*>(out + (size_t)(row + 8) * KDIM + col) = o1;
        }
    }
}

extern "C" void kernel_launch(void* const* d_in, const int* in_sizes, int n_in,
                              void* d_out, int out_size)
{
    const float* x    = (const float*)d_in[0];   // [512, 4096]
    const float* w    = (const float*)d_in[1];   // [512, 512, 8, 8]
    const float* bias = (const float*)d_in[2];   // [512, 8] -> flat [4096]
    float* out = (float*)d_out;                  // [512, 4096]

    cudaFuncSetAttribute(octonion_mma_v3,
                         cudaFuncAttributeMaxDynamicSharedMemorySize, SMEM_BYTES);
    dim3 grid(KDIM / 128, 512 / 128);            // (32, 4) = 128 CTAs
    octonion_mma_v3<<<grid, 256, SMEM_BYTES>>>(x, w, bias, out);
}

// round 7
// speedup vs baseline: 3.8128x; 1.0682x over previous
#include <cuda_runtime.h>
#include <cuda_fp16.h>
#include <cstdint>

#define KDIM 4096
#define BK 32
#define NKB 128
// smem: 2 stages x (A2 128x16 words + B2 128x16 words), word = f16x2
#define STG_WORDS 4096
#define A_WORDS 2048

__device__ __forceinline__ void mma_f16(float* d, const uint32_t* a, const uint32_t* b) {
    asm volatile(
        "mma.sync.aligned.m16n8k16.row.col.f32.f16.f16.f32 "
        "{%0,%1,%2,%3}, {%4,%5,%6,%7}, {%8,%9}, {%0,%1,%2,%3};"
        : "+f"(d[0]), "+f"(d[1]), "+f"(d[2]), "+f"(d[3])
        : "r"(a[0]), "r"(a[1]), "r"(a[2]), "r"(a[3]),
          "r"(b[0]), "r"(b[1]));
}

__device__ __forceinline__ uint32_t pack2(float lo, float hi) {
    __half2 h = __floats2half2_rn(lo, hi);
    return *reinterpret_cast<uint32_t*>(&h);
}

__global__ __launch_bounds__(256, 1)
void octonion_f16_kernel(const float* __restrict__ x,
                         const float* __restrict__ w,
                         const float* __restrict__ bias,
                         float* __restrict__ out)
{
    __shared__ uint32_t sm2[2 * STG_WORDS];   // 32 KB

    const int tid  = threadIdx.x;
    const int lane = tid & 31;
    const int warp = tid >> 5;
    const int wm   = warp >> 2;          // 0..1 -> 64-row strip
    const int wn   = warp & 3;           // 0..3 -> 32-col strip
    const int g    = lane >> 2;
    const int cc   = lane & 3;
    const uint32_t sw = 4u * ((g >> 1) & 3);

    const int row0 = blockIdx.y * 128;
    const int col0 = blockIdx.x * 128;
    const int oct0 = col0 >> 3;

    // ---- loader descriptors ----
    // A: rows mA+32i, k-quad q (float4). word = m*16 + (2q ^ swA)
    const int mA = tid >> 3, q = tid & 7;
    const uint32_t swA = 4u * (((tid >> 3) >> 1) & 3);
    const float* aSrc = x + (size_t)(row0 + mA) * KDIM + q * 4;
    // B: octonion oi, k-pair u (k = 2u, 2u+1), halves h = 0,1
    const int oi = tid >> 4, u = tid & 15;
    const float* bSrc = w + (size_t)(oct0 + oi) * 32768 + u * 16;
    // B word for (h, j): n = oi*8 + 4h + j
    uint32_t bW[2][4];
    #pragma unroll
    for (int h = 0; h < 2; ++h)
        #pragma unroll
        for (int j = 0; j < 4; ++j) {
            const int n = oi * 8 + 4 * h + j;
            bW[h][j] = A_WORDS + n * 16 +
                       ((uint32_t)u ^ (4u * ((uint32_t)(2 * h + (j >> 1)) & 3))
                                    ^ (8u * ((uint32_t)oi & 1)));
        }
    uint32_t aW[4];
    #pragma unroll
    for (int i = 0; i < 4; ++i)
        aW[i] = (mA + 32 * i) * 16 + ((uint32_t)(2 * q) ^ swA);

    // ---- fragment word bases ----
    // A frag word: (wm*64 + mt*16 + 8*pr + g)*16 + ((8ks + cc + 4e) ^ sw)
    const uint32_t aFB = (uint32_t)(wm * 64 + g) * 16;
    // B frag word: A_WORDS + (wn*32 + nt*8 + g)*16 + ((8ks + cc + 4r) ^ sw ^ 8(nt&1))
    const uint32_t bFB = A_WORDS + (uint32_t)(wn * 32 + g) * 16;

    float acc[4][4][4];
    #pragma unroll
    for (int i = 0; i < 4; ++i)
        #pragma unroll
        for (int j = 0; j < 4; ++j)
            #pragma unroll
            for (int r = 0; r < 4; ++r)
                acc[i][j][r] = 0.0f;

    float4 rA[4], rBa[2], rBb[2];

    // ---- prologue: load + convert kb=0 into stage 0 ----
    #pragma unroll
    for (int i = 0; i < 4; ++i)
        rA[i] = *reinterpret_cast<const float4*>(aSrc + (size_t)i * 32 * KDIM);
    #pragma unroll
    for (int h = 0; h < 2; ++h) {
        rBa[h] = *reinterpret_cast<const float4*>(bSrc + 4 * h);
        rBb[h] = *reinterpret_cast<const float4*>(bSrc + 8 + 4 * h);
    }
    #pragma unroll
    for (int i = 0; i < 4; ++i) {
        sm2[aW[i]]     = pack2(rA[i].x, rA[i].y);
        sm2[aW[i] + 1] = pack2(rA[i].z, rA[i].w);
    }
    #pragma unroll
    for (int h = 0; h < 2; ++h) {
        sm2[bW[h][0]] = pack2(rBa[h].x, rBb[h].x);
        sm2[bW[h][1]] = pack2(rBa[h].y, rBb[h].y);
        sm2[bW[h][2]] = pack2(rBa[h].z, rBb[h].z);
        sm2[bW[h][3]] = pack2(rBa[h].w, rBb[h].w);
    }
    __syncthreads();

    for (int kb = 0; kb < NKB; ++kb) {
        // prefetch next k-block to registers
        if (kb + 1 < NKB) {
            const float* as = aSrc + (kb + 1) * BK;
            const float* bs = bSrc + (kb + 1) * 256;
            #pragma unroll
            for (int i = 0; i < 4; ++i)
                rA[i] = *reinterpret_cast<const float4*>(as + (size_t)i * 32 * KDIM);
            #pragma unroll
            for (int h = 0; h < 2; ++h) {
                rBa[h] = *reinterpret_cast<const float4*>(bs + 4 * h);
                rBb[h] = *reinterpret_cast<const float4*>(bs + 8 + 4 * h);
            }
        }

        // ---- compute current stage ----
        const uint32_t so = (kb & 1) * STG_WORDS;
        #pragma unroll
        for (int ks = 0; ks < 2; ++ks) {
            uint32_t a[4][4], b[4][2];
            #pragma unroll
            for (int mt = 0; mt < 4; ++mt)
                #pragma unroll
                for (int r = 0; r < 4; ++r) {
                    const int pr = r & 1, e = r >> 1;
                    a[mt][r] = sm2[so + aFB + (uint32_t)(mt * 16 + 8 * pr) * 16
                                   + ((uint32_t)(8 * ks + cc + 4 * e) ^ sw)];
                }
            #pragma unroll
            for (int nt = 0; nt < 4; ++nt)
                #pragma unroll
                for (int r = 0; r < 2; ++r)
                    b[nt][r] = sm2[so + bFB + (uint32_t)(nt * 8) * 16
                                   + ((uint32_t)(8 * ks + cc + 4 * r) ^ sw
                                      ^ (8u * (nt & 1)))];
            #pragma unroll
            for (int mt = 0; mt < 4; ++mt)
                #pragma unroll
                for (int nt = 0; nt < 4; ++nt)
                    mma_f16(acc[mt][nt], a[mt], b[nt]);
        }

        // ---- convert + store next stage ----
        if (kb + 1 < NKB) {
            const uint32_t sn = ((kb + 1) & 1) * STG_WORDS;
            #pragma unroll
            for (int i = 0; i < 4; ++i) {
                sm2[sn + aW[i]]     = pack2(rA[i].x, rA[i].y);
                sm2[sn + aW[i] + 1] = pack2(rA[i].z, rA[i].w);
            }
            #pragma unroll
            for (int h = 0; h < 2; ++h) {
                sm2[sn + bW[h][0]] = pack2(rBa[h].x, rBb[h].x);
                sm2[sn + bW[h][1]] = pack2(rBa[h].y, rBb[h].y);
                sm2[sn + bW[h][2]] = pack2(rBa[h].z, rBb[h].z);
                sm2[sn + bW[h][3]] = pack2(rBa[h].w, rBb[h].w);
            }
        }
        __syncthreads();
    }

    // ---- epilogue: + bias, float2 stores ----
    #pragma unroll
    for (int mt = 0; mt < 4; ++mt) {
        const int row = row0 + wm * 64 + mt * 16 + g;
        #pragma unroll
        for (int nt = 0; nt < 4; ++nt) {
            const int col = col0 + wn * 32 + nt * 8 + cc * 2;
            const float2 bb = *reinterpret_cast<const float2*>(bias + col);
            float2 o0, o1;
            o0.x = acc[mt][nt][0] + bb.x;
            o0.y = acc[mt][nt][1] + bb.y;
            o1.x = acc[mt][nt][2] + bb.x;
            o1.y = acc[mt][nt][3] + bb.y;
            *reinterpret_cast<float2*>(out + (size_t)row * KDIM + col) = o0;
            *reinterpret_cast<float2*>(out + (size_t)(row + 8) * KDIM + col) = o1;
        }
    }
}

extern "C" void kernel_launch(void* const* d_in, const int* in_sizes, int n_in,
                              void* d_out, int out_size)
{
    const float* x    = (const float*)d_in[0];   // [512, 4096]
    const float* w    = (const float*)d_in[1];   // [512, 512, 8, 8]
    const float* bias = (const float*)d_in[2];   // [512, 8] -> flat [4096]
    float* out = (float*)d_out;                  // [512, 4096]

    dim3 grid(KDIM / 128, 512 / 128);            // (32, 4) = 128 CTAs
    octonion_f16_kernel<<<grid, 256>>>(x, w, bias, out);
}

// round 8
// speedup vs baseline: 6.6005x; 1.7312x over previous
#include <cuda_runtime.h>
#include <cuda_fp16.h>
#include <cstdint>

#define KDIM 4096
#define BK 64
#define NKB (KDIM / BK)        // 64
#define STG_BYTES 32768        // A 16KB + B 16KB (fp16)
#define NSTAGE 4
#define SMEM_BYTES (NSTAGE * STG_BYTES)  // 131072

// ---- scratch: fp16 copies (static device arrays; no runtime alloc) ----
__device__ __half g_xh[512 * 4096];          // A[m][k]
__device__ __half g_wh[4096ull * 4096];      // B[n][k]

// ============ converters ============
__global__ void cvt_x_kernel(const float* __restrict__ x) {
    const int i = blockIdx.x * 256 + threadIdx.x;      // float4 index
    const float4 v = reinterpret_cast<const float4*>(x)[i];
    __half2* dst = reinterpret_cast<__half2*>(g_xh);
    dst[2 * i]     = __floats2half2_rn(v.x, v.y);
    dst[2 * i + 1] = __floats2half2_rn(v.z, v.w);
}

// w[i,j,p,q] -> wh[n=i*8+q][kk=j*8+p]
__global__ void cvt_w_kernel(const float* __restrict__ w) {
    const int i  = blockIdx.x;          // 0..511
    const int t  = threadIdx.x;         // 256
    const int j0 = t >> 3, q = t & 7;
    #pragma unroll 4
    for (int jg = 0; jg < 16; ++jg) {
        const int j = jg * 32 + j0;
        const float* src = w + (size_t)i * 32768 + j * 64 + q;
        __half h[8];
        #pragma unroll
        for (int p = 0; p < 8; ++p) h[p] = __float2half_rn(src[p * 8]);
        *reinterpret_cast<uint4*>(g_wh + (size_t)(i * 8 + q) * 4096 + j * 8) =
            *reinterpret_cast<uint4*>(h);
    }
}

// ============ GEMM ============
__device__ __forceinline__ uint32_t smem_u32(const void* p) {
    uint32_t a;
    asm("{ .reg .u64 t; cvta.to.shared.u64 t, %1; cvt.u32.u64 %0, t; }" : "=r"(a) : "l"(p));
    return a;
}
__device__ __forceinline__ void cp16(uint32_t dst, const void* src) {
    asm volatile("cp.async.cg.shared.global [%0], [%1], 16;" :: "r"(dst), "l"(src));
}
__device__ __forceinline__ void ldsm_x4(uint32_t* r, uint32_t addr) {
    asm volatile("ldmatrix.sync.aligned.m8n8.x4.shared.b16 {%0,%1,%2,%3}, [%4];"
                 : "=r"(r[0]), "=r"(r[1]), "=r"(r[2]), "=r"(r[3]) : "r"(addr));
}
__device__ __forceinline__ void mma_f16(float* d, const uint32_t* a, const uint32_t* b) {
    asm volatile(
        "mma.sync.aligned.m16n8k16.row.col.f32.f16.f16.f32 "
        "{%0,%1,%2,%3}, {%4,%5,%6,%7}, {%8,%9}, {%0,%1,%2,%3};"
        : "+f"(d[0]), "+f"(d[1]), "+f"(d[2]), "+f"(d[3])
        : "r"(a[0]), "r"(a[1]), "r"(a[2]), "r"(a[3]),
          "r"(b[0]), "r"(b[1]));
}

__global__ __launch_bounds__(256, 1)
void octonion_gemm_f16(const float* __restrict__ bias, float* __restrict__ out)
{
    extern __shared__ char smem[];
    const uint32_t sbase = smem_u32(smem);

    const int tid  = threadIdx.x;
    const int lane = tid & 31;
    const int warp = tid >> 5;
    const int wm   = warp >> 2;          // 0..1 -> 64-row strip
    const int wn   = warp & 3;           // 0..3 -> 32-col strip
    const int row0 = blockIdx.y * 128;
    const int col0 = blockIdx.x * 128;

    // ---- loader: 4 A chunks + 4 B chunks (16B each) per thread per stage ----
    const int lm = tid >> 3;             // base row (A: m, B: n), +32*i
    const int lu = tid & 7;              // 16B unit within 128B row
    const __half* aSrc = g_xh + (size_t)(row0 + lm) * KDIM + lu * 8;
    const __half* bSrc = g_wh + (size_t)(col0 + lm) * KDIM + lu * 8;
    uint32_t aDst[4], bDst[4];
    #pragma unroll
    for (int i = 0; i < 4; ++i) {
        const int r = lm + 32 * i;
        aDst[i] = (uint32_t)(r * 128 + ((lu ^ (r & 7)) << 4));
        bDst[i] = 16384u + aDst[i];
    }

    float acc[4][4][4];
    #pragma unroll
    for (int i = 0; i < 4; ++i)
        #pragma unroll
        for (int j = 0; j < 4; ++j)
            #pragma unroll
            for (int r = 0; r < 4; ++r)
                acc[i][j][r] = 0.0f;

    // ---- prologue: 3 stages ----
    #pragma unroll
    for (int s = 0; s < 3; ++s) {
        const uint32_t so = sbase + s * STG_BYTES;
        #pragma unroll
        for (int i = 0; i < 4; ++i) {
            cp16(so + aDst[i], aSrc + (size_t)(s * BK) + (size_t)(32 * i) * KDIM);
            cp16(so + bDst[i], bSrc + (size_t)(s * BK) + (size_t)(32 * i) * KDIM);
        }
        asm volatile("cp.async.commit_group;" ::: "memory");
    }

    // ---- fragment address bases (row part; unit varies per ks) ----
    const int arow = wm * 64 + (lane & 15);     // + mt*16
    const int brow = wn * 32 + (lane & 15);     // + ntp*16
    const int ubit = lane >> 4;                  // upper/lower 16B of k16

    for (int kb = 0; kb < NKB; ++kb) {
        asm volatile("cp.async.wait_group 2;" ::: "memory");
        __syncthreads();

        const uint32_t so = sbase + (kb & 3) * STG_BYTES;

        #pragma unroll
        for (int ks = 0; ks < 4; ++ks) {
            uint32_t a[4][4], b[4][2];
            #pragma unroll
            for (int mt = 0; mt < 4; ++mt) {
                const int r = arow + mt * 16;
                const int u = (2 * ks + ubit) ^ (r & 7);
                ldsm_x4(a[mt], so + (uint32_t)(r * 128 + u * 16));
            }
            #pragma unroll
            for (int ntp = 0; ntp < 2; ++ntp) {
                const int r = brow + ntp * 16;
                const int u = (2 * ks + ubit) ^ (r & 7);
                uint32_t t[4];
                ldsm_x4(t, so + 16384u + (uint32_t)(r * 128 + u * 16));
                b[2 * ntp][0]     = t[0];
                b[2 * ntp + 1][0] = t[1];
                b[2 * ntp][1]     = t[2];
                b[2 * ntp + 1][1] = t[3];
            }
            #pragma unroll
            for (int mt = 0; mt < 4; ++mt)
                #pragma unroll
                for (int nt = 0; nt < 4; ++nt)
                    mma_f16(acc[mt][nt], a[mt], b[nt]);
        }

        if (kb + 3 < NKB) {
            const uint32_t sn = sbase + ((kb + 3) & 3) * STG_BYTES;
            const size_t ko = (size_t)(kb + 3) * BK;
            #pragma unroll
            for (int i = 0; i < 4; ++i) {
                cp16(sn + aDst[i], aSrc + ko + (size_t)(32 * i) * KDIM);
                cp16(sn + bDst[i], bSrc + ko + (size_t)(32 * i) * KDIM);
            }
            asm volatile("cp.async.commit_group;" ::: "memory");
        }
    }

    // ---- epilogue: + bias, float2 stores ----
    #pragma unroll
    for (int mt = 0; mt < 4; ++mt) {
        const int row = row0 + wm * 64 + mt * 16 + (lane >> 2);
        #pragma unroll
        for (int nt = 0; nt < 4; ++nt) {
            const int col = col0 + wn * 32 + nt * 8 + (lane & 3) * 2;
            const float2 bb = *reinterpret_cast<const float2*>(bias + col);
            float2 o0, o1;
            o0.x = acc[mt][nt][0] + bb.x;
            o0.y = acc[mt][nt][1] + bb.y;
            o1.x = acc[mt][nt][2] + bb.x;
            o1.y = acc[mt][nt][3] + bb.y;
            *reinterpret_cast<float2*>(out + (size_t)row * KDIM + col) = o0;
            *reinterpret_cast<float2*>(out + (size_t)(row + 8) * KDIM + col) = o1;
        }
    }
}

extern "C" void kernel_launch(void* const* d_in, const int* in_sizes, int n_in,
                              void* d_out, int out_size)
{
    const float* x    = (const float*)d_in[0];   // [512, 4096]
    const float* w    = (const float*)d_in[1];   // [512, 512, 8, 8]
    const float* bias = (const float*)d_in[2];   // [512, 8] -> flat [4096]
    float* out = (float*)d_out;                  // [512, 4096]

    cvt_x_kernel<<<512 * 4096 / 4 / 256, 256>>>(x);
    cvt_w_kernel<<<512, 256>>>(w);

    cudaFuncSetAttribute(octonion_gemm_f16,
                         cudaFuncAttributeMaxDynamicSharedMemorySize, SMEM_BYTES);
    dim3 grid(KDIM / 128, 512 / 128);            // (32, 4) = 128 CTAs
    octonion_gemm_f16<<<grid, 256, SMEM_BYTES>>>(bias, out);
}

// round 9
// speedup vs baseline: 6.9001x; 1.0454x over previous
#include <cuda_runtime.h>
#include <cuda_fp16.h>
#include <cstdint>

#define KDIM 4096
#define BK 128
#define NKB (KDIM / BK)        // 32
#define STG_BYTES 65536        // A 32KB + B 32KB (fp16)
#define NSTAGE 3
#define SMEM_BYTES (NSTAGE * STG_BYTES)  // 196608

// ---- scratch: fp16 copies (static device arrays; no runtime alloc) ----
__device__ __half g_xh[512 * 4096];          // A[m][k]
__device__ __half g_wh[4096ull * 4096];      // B[n][k]

// ============ merged converter ============
// blocks [0,2048): w[i,j,p,q] -> wh[n=i*8+q][kk=j*8+p]   (i = b>>2, j-quarter = b&3)
// blocks [2048,4096): x -> xh (float4 -> 2x half2)
__global__ void cvt_kernel(const float* __restrict__ x, const float* __restrict__ w) {
    const int b = blockIdx.x;
    const int t = threadIdx.x;
    if (b < 2048) {
        const int i  = b >> 2;
        const int j0 = t >> 3, q = t & 7;
        #pragma unroll
        for (int jj = 0; jj < 4; ++jj) {
            const int j = (b & 3) * 128 + jj * 32 + j0;
            const float* src = w + (size_t)i * 32768 + j * 64 + q;
            __half h[8];
            #pragma unroll
            for (int p = 0; p < 8; ++p) h[p] = __float2half_rn(src[p * 8]);
            *reinterpret_cast<uint4*>(g_wh + (size_t)(i * 8 + q) * 4096 + j * 8) =
                *reinterpret_cast<uint4*>(h);
        }
    } else {
        const int i = (b - 2048) * 256 + t;            // float4 index
        const float4 v = reinterpret_cast<const float4*>(x)[i];
        __half2* dst = reinterpret_cast<__half2*>(g_xh);
        dst[2 * i]     = __floats2half2_rn(v.x, v.y);
        dst[2 * i + 1] = __floats2half2_rn(v.z, v.w);
    }
}

// ============ GEMM ============
__device__ __forceinline__ uint32_t smem_u32(const void* p) {
    uint32_t a;
    asm("{ .reg .u64 t; cvta.to.shared.u64 t, %1; cvt.u32.u64 %0, t; }" : "=r"(a) : "l"(p));
    return a;
}
__device__ __forceinline__ void cp16(uint32_t dst, const void* src) {
    asm volatile("cp.async.cg.shared.global [%0], [%1], 16;" :: "r"(dst), "l"(src));
}
__device__ __forceinline__ void ldsm_x4(uint32_t* r, uint32_t addr) {
    asm volatile("ldmatrix.sync.aligned.m8n8.x4.shared.b16 {%0,%1,%2,%3}, [%4];"
                 : "=r"(r[0]), "=r"(r[1]), "=r"(r[2]), "=r"(r[3]) : "r"(addr));
}
__device__ __forceinline__ void mma_f16(float* d, const uint32_t* a, const uint32_t* b) {
    asm volatile(
        "mma.sync.aligned.m16n8k16.row.col.f32.f16.f16.f32 "
        "{%0,%1,%2,%3}, {%4,%5,%6,%7}, {%8,%9}, {%0,%1,%2,%3};"
        : "+f"(d[0]), "+f"(d[1]), "+f"(d[2]), "+f"(d[3])
        : "r"(a[0]), "r"(a[1]), "r"(a[2]), "r"(a[3]),
          "r"(b[0]), "r"(b[1]));
}

__global__ __launch_bounds__(256, 1)
void octonion_gemm_f16(const float* __restrict__ bias, float* __restrict__ out)
{
    extern __shared__ char smem[];
    const uint32_t sbase = smem_u32(smem);

    const int tid  = threadIdx.x;
    const int lane = tid & 31;
    const int warp = tid >> 5;
    const int wm   = warp >> 2;          // 0..1 -> 64-row strip
    const int wn   = warp & 3;           // 0..3 -> 32-col strip
    const int row0 = blockIdx.y * 128;
    const int col0 = blockIdx.x * 128;

    // ---- loader: 8 A + 8 B 16B chunks per thread per stage ----
    // chunk (r = (t>>4)+16i, u = t&15): smem byte = r*256 + ((u ^ (r&7))*16)
    const int lr = tid >> 4;
    const int lu = tid & 15;
    const __half* aSrc = g_xh + (size_t)(row0 + lr) * KDIM + lu * 8;
    const __half* bSrc = g_wh + (size_t)(col0 + lr) * KDIM + lu * 8;
    uint32_t aDst[8];
    #pragma unroll
    for (int i = 0; i < 8; ++i) {
        const int r = lr + 16 * i;
        aDst[i] = (uint32_t)(r * 256 + (((uint32_t)lu ^ (r & 7)) << 4));
    }

    float acc[4][4][4];
    #pragma unroll
    for (int i = 0; i < 4; ++i)
        #pragma unroll
        for (int j = 0; j < 4; ++j)
            #pragma unroll
            for (int r = 0; r < 4; ++r)
                acc[i][j][r] = 0.0f;

    // ---- prologue: 2 stages in flight ----
    #pragma unroll
    for (int s = 0; s < 2; ++s) {
        const uint32_t so = sbase + s * STG_BYTES;
        #pragma unroll
        for (int i = 0; i < 8; ++i) {
            cp16(so + aDst[i],          aSrc + (size_t)(s * BK) + (size_t)(16 * i) * KDIM);
            cp16(so + 32768u + aDst[i], bSrc + (size_t)(s * BK) + (size_t)(16 * i) * KDIM);
        }
        asm volatile("cp.async.commit_group;" ::: "memory");
    }

    const int arow = wm * 64 + (lane & 15);     // + mt*16
    const int brow = wn * 32 + (lane & 15);     // + ntp*16
    const int ubit = lane >> 4;                  // k-half within k16

    int sidx = 0;
    for (int kb = 0; kb < NKB; ++kb) {
        asm volatile("cp.async.wait_group 1;" ::: "memory");
        __syncthreads();

        const uint32_t so = sbase + sidx * STG_BYTES;

        #pragma unroll
        for (int ks = 0; ks < 8; ++ks) {
            uint32_t a[4][4], b[4][2];
            #pragma unroll
            for (int mt = 0; mt < 4; ++mt) {
                const int r = arow + mt * 16;
                const uint32_t u = (uint32_t)(2 * ks + ubit) ^ (r & 7);
                ldsm_x4(a[mt], so + (uint32_t)(r * 256) + (u << 4));
            }
            #pragma unroll
            for (int ntp = 0; ntp < 2; ++ntp) {
                const int r = brow + ntp * 16;
                const uint32_t u = (uint32_t)(2 * ks + ubit) ^ (r & 7);
                uint32_t t4[4];
                ldsm_x4(t4, so + 32768u + (uint32_t)(r * 256) + (u << 4));
                b[2 * ntp][0]     = t4[0];
                b[2 * ntp + 1][0] = t4[1];
                b[2 * ntp][1]     = t4[2];
                b[2 * ntp + 1][1] = t4[3];
            }
            #pragma unroll
            for (int mt = 0; mt < 4; ++mt)
                #pragma unroll
                for (int nt = 0; nt < 4; ++nt)
                    mma_f16(acc[mt][nt], a[mt], b[nt]);
        }

        if (kb + 2 < NKB) {
            const uint32_t sn = sbase + ((sidx + 2) % NSTAGE) * STG_BYTES;
            const size_t ko = (size_t)(kb + 2) * BK;
            #pragma unroll
            for (int i = 0; i < 8; ++i) {
                cp16(sn + aDst[i],          aSrc + ko + (size_t)(16 * i) * KDIM);
                cp16(sn + 32768u + aDst[i], bSrc + ko + (size_t)(16 * i) * KDIM);
            }
            asm volatile("cp.async.commit_group;" ::: "memory");
        }
        sidx = (sidx + 1) % NSTAGE;
    }

    // ---- epilogue: + bias, float2 stores ----
    #pragma unroll
    for (int mt = 0; mt < 4; ++mt) {
        const int row = row0 + wm * 64 + mt * 16 + (lane >> 2);
        #pragma unroll
        for (int nt = 0; nt < 4; ++nt) {
            const int col = col0 + wn * 32 + nt * 8 + (lane & 3) * 2;
            const float2 bb = *reinterpret_cast<const float2*>(bias + col);
            float2 o0, o1;
            o0.x = acc[mt][nt][0] + bb.x;
            o0.y = acc[mt][nt][1] + bb.y;
            o1.x = acc[mt][nt][2] + bb.x;
            o1.y = acc[mt][nt][3] + bb.y;
            *reinterpret_cast<float2*>(out + (size_t)row * KDIM + col) = o0;
            *reinterpret_cast<float2*>(out + (size_t)(row + 8) * KDIM + col) = o1;
        }
    }
}

extern "C" void kernel_launch(void* const* d_in, const int* in_sizes, int n_in,
                              void* d_out, int out_size)
{
    const float* x    = (const float*)d_in[0];   // [512, 4096]
    const float* w    = (const float*)d_in[1];   // [512, 512, 8, 8]
    const float* bias = (const float*)d_in[2];   // [512, 8] -> flat [4096]
    float* out = (float*)d_out;                  // [512, 4096]

    cvt_kernel<<<4096, 256>>>(x, w);

    cudaFuncSetAttribute(octonion_gemm_f16,
                         cudaFuncAttributeMaxDynamicSharedMemorySize, SMEM_BYTES);
    dim3 grid(KDIM / 128, 512 / 128);            // (32, 4) = 128 CTAs
    octonion_gemm_f16<<<grid, 256, SMEM_BYTES>>>(bias, out);
}

// round 10
// speedup vs baseline: 7.0834x; 1.0266x over previous
#include <cuda_runtime.h>
#include <cuda_fp16.h>
#include <cstdint>

#define KDIM 4096
#define BK 64
#define NKB (KDIM / BK)        // 64
#define A_BYTES 8192           // 64 rows x 128B
#define B_BYTES 16384          // 128 rows x 128B
#define STG_BYTES (A_BYTES + B_BYTES)   // 24576
#define NSTAGE 4
#define SMEM_BYTES (NSTAGE * STG_BYTES) // 98304

// ---- scratch: fp16 copies (static device arrays; no runtime alloc) ----
__device__ __half g_xh[512 * 4096];          // A[m][k]
__device__ __half g_wh[4096ull * 4096];      // B[n][k]

// ============ merged converter ============
__global__ void cvt_kernel(const float* __restrict__ x, const float* __restrict__ w) {
    const int b = blockIdx.x;
    const int t = threadIdx.x;
    if (b < 2048) {
        const int i  = b >> 2;
        const int j0 = t >> 3, q = t & 7;
        #pragma unroll
        for (int jj = 0; jj < 4; ++jj) {
            const int j = (b & 3) * 128 + jj * 32 + j0;
            const float* src = w + (size_t)i * 32768 + j * 64 + q;
            __half h[8];
            #pragma unroll
            for (int p = 0; p < 8; ++p) h[p] = __float2half_rn(src[p * 8]);
            *reinterpret_cast<uint4*>(g_wh + (size_t)(i * 8 + q) * 4096 + j * 8) =
                *reinterpret_cast<uint4*>(h);
        }
    } else {
        const int i = (b - 2048) * 256 + t;            // float4 index
        const float4 v = reinterpret_cast<const float4*>(x)[i];
        __half2* dst = reinterpret_cast<__half2*>(g_xh);
        dst[2 * i]     = __floats2half2_rn(v.x, v.y);
        dst[2 * i + 1] = __floats2half2_rn(v.z, v.w);
    }
}

// ============ GEMM ============
__device__ __forceinline__ uint32_t smem_u32(const void* p) {
    uint32_t a;
    asm("{ .reg .u64 t; cvta.to.shared.u64 t, %1; cvt.u32.u64 %0, t; }" : "=r"(a) : "l"(p));
    return a;
}
__device__ __forceinline__ void cp16(uint32_t dst, const void* src) {
    asm volatile("cp.async.cg.shared.global [%0], [%1], 16;" :: "r"(dst), "l"(src));
}
__device__ __forceinline__ void ldsm_x4(uint32_t* r, uint32_t addr) {
    asm volatile("ldmatrix.sync.aligned.m8n8.x4.shared.b16 {%0,%1,%2,%3}, [%4];"
                 : "=r"(r[0]), "=r"(r[1]), "=r"(r[2]), "=r"(r[3]) : "r"(addr));
}
__device__ __forceinline__ void mma_f16(float* d, const uint32_t* a, const uint32_t* b) {
    asm volatile(
        "mma.sync.aligned.m16n8k16.row.col.f32.f16.f16.f32 "
        "{%0,%1,%2,%3}, {%4,%5,%6,%7}, {%8,%9}, {%0,%1,%2,%3};"
        : "+f"(d[0]), "+f"(d[1]), "+f"(d[2]), "+f"(d[3])
        : "r"(a[0]), "r"(a[1]), "r"(a[2]), "r"(a[3]),
          "r"(b[0]), "r"(b[1]));
}

__global__ __launch_bounds__(256, 2)
void octonion_gemm_f16(const float* __restrict__ bias, float* __restrict__ out)
{
    extern __shared__ char smem[];
    const uint32_t sbase = smem_u32(smem);

    const int tid  = threadIdx.x;
    const int lane = tid & 31;
    const int warp = tid >> 5;
    const int wm   = warp >> 2;          // 0..1 -> 32-row strip
    const int wn   = warp & 3;           // 0..3 -> 32-col strip
    const int row0 = blockIdx.y * 64;
    const int col0 = blockIdx.x * 128;

    // ---- loader: 2 A + 4 B 16B chunks per thread per stage ----
    const int lr = tid >> 3;             // 0..31
    const int lu = tid & 7;              // 16B unit within 128B row
    const __half* aSrc = g_xh + (size_t)(row0 + lr) * KDIM + lu * 8;
    const __half* bSrc = g_wh + (size_t)(col0 + lr) * KDIM + lu * 8;
    uint32_t dstOff[4];
    #pragma unroll
    for (int i = 0; i < 4; ++i) {
        const int r = lr + 32 * i;
        dstOff[i] = (uint32_t)((r & 63) * 128 + (((uint32_t)lu ^ (r & 7)) << 4));
    }

    float acc[2][4][4];
    #pragma unroll
    for (int i = 0; i < 2; ++i)
        #pragma unroll
        for (int j = 0; j < 4; ++j)
            #pragma unroll
            for (int r = 0; r < 4; ++r)
                acc[i][j][r] = 0.0f;

    // ---- prologue: 3 stages in flight ----
    #pragma unroll
    for (int s = 0; s < 3; ++s) {
        const uint32_t so = sbase + s * STG_BYTES;
        #pragma unroll
        for (int i = 0; i < 2; ++i)
            cp16(so + dstOff[i], aSrc + (size_t)(s * BK) + (size_t)(32 * i) * KDIM);
        #pragma unroll
        for (int i = 0; i < 4; ++i)
            cp16(so + A_BYTES + dstOff[i] + (uint32_t)(i >> 1) * 8192,
                 bSrc + (size_t)(s * BK) + (size_t)(32 * i) * KDIM);
        asm volatile("cp.async.commit_group;" ::: "memory");
    }

    const int arow = wm * 32 + (lane & 15);     // + mt*16
    const int brow = wn * 32 + (lane & 15);     // + ntp*16
    const int ubit = lane >> 4;

    for (int kb = 0; kb < NKB; ++kb) {
        asm volatile("cp.async.wait_group 2;" ::: "memory");
        __syncthreads();

        const uint32_t so = sbase + (kb & 3) * STG_BYTES;

        #pragma unroll
        for (int ks = 0; ks < 4; ++ks) {
            uint32_t a[2][4], b[4][2];
            #pragma unroll
            for (int mt = 0; mt < 2; ++mt) {
                const int r = arow + mt * 16;
                const uint32_t u = (uint32_t)(2 * ks + ubit) ^ (r & 7);
                ldsm_x4(a[mt], so + (uint32_t)(r * 128) + (u << 4));
            }
            #pragma unroll
            for (int ntp = 0; ntp < 2; ++ntp) {
                const int r = brow + ntp * 16;
                const uint32_t u = (uint32_t)(2 * ks + ubit) ^ (r & 7);
                uint32_t t4[4];
                ldsm_x4(t4, so + A_BYTES + (uint32_t)(r * 128) + (u << 4));
                b[2 * ntp][0]     = t4[0];
                b[2 * ntp + 1][0] = t4[1];
                b[2 * ntp][1]     = t4[2];
                b[2 * ntp + 1][1] = t4[3];
            }
            #pragma unroll
            for (int mt = 0; mt < 2; ++mt)
                #pragma unroll
                for (int nt = 0; nt < 4; ++nt)
                    mma_f16(acc[mt][nt], a[mt], b[nt]);
        }

        if (kb + 3 < NKB) {
            const uint32_t sn = sbase + ((kb + 3) & 3) * STG_BYTES;
            const size_t ko = (size_t)(kb + 3) * BK;
            #pragma unroll
            for (int i = 0; i < 2; ++i)
                cp16(sn + dstOff[i], aSrc + ko + (size_t)(32 * i) * KDIM);
            #pragma unroll
            for (int i = 0; i < 4; ++i)
                cp16(sn + A_BYTES + dstOff[i] + (uint32_t)(i >> 1) * 8192,
                     bSrc + ko + (size_t)(32 * i) * KDIM);
            asm volatile("cp.async.commit_group;" ::: "memory");
        }
    }

    // ---- epilogue: + bias, float2 stores ----
    #pragma unroll
    for (int mt = 0; mt < 2; ++mt) {
        const int row = row0 + wm * 32 + mt * 16 + (lane >> 2);
        #pragma unroll
        for (int nt = 0; nt < 4; ++nt) {
            const int col = col0 + wn * 32 + nt * 8 + (lane & 3) * 2;
            const float2 bb = *reinterpret_cast<const float2*>(bias + col);
            float2 o0, o1;
            o0.x = acc[mt][nt][0] + bb.x;
            o0.y = acc[mt][nt][1] + bb.y;
            o1.x = acc[mt][nt][2] + bb.x;
            o1.y = acc[mt][nt][3] + bb.y;
            *reinterpret_cast<float2*>(out + (size_t)row * KDIM + col) = o0;
            *reinterpret_cast<float2*>(out + (size_t)(row + 8) * KDIM + col) = o1;
        }
    }
}

extern "C" void kernel_launch(void* const* d_in, const int* in_sizes, int n_in,
                              void* d_out, int out_size)
{
    const float* x    = (const float*)d_in[0];   // [512, 4096]
    const float* w    = (const float*)d_in[1];   // [512, 512, 8, 8]
    const float* bias = (const float*)d_in[2];   // [512, 8] -> flat [4096]
    float* out = (float*)d_out;                  // [512, 4096]

    cvt_kernel<<<4096, 256>>>(x, w);

    cudaFuncSetAttribute(octonion_gemm_f16,
                         cudaFuncAttributeMaxDynamicSharedMemorySize, SMEM_BYTES);
    dim3 grid(KDIM / 128, 512 / 64);             // (32, 8) = 256 CTAs
    octonion_gemm_f16<<<grid, 256, SMEM_BYTES>>>(bias, out);
}